// round 9
// baseline (speedup 1.0000x reference)
#include <cuda_runtime.h>
#include <cuda_bf16.h>
#include <cstdint>

#define LSEQ 4096
#define DIN  512
#define NH   8
#define NB   2
#define NCTA 128

typedef unsigned short ushort_t;
static const size_t bS = 512 * 512;
static const size_t bX = (size_t)LSEQ * DIN;

// ---------------- device scratch ----------------
__device__ __align__(256) ushort_t g_xh [NB * LSEQ * DIN];
__device__ __align__(256) ushort_t g_xl [NB * LSEQ * DIN];
__device__ __align__(256) ushort_t g_xTh[NB * DIN * LSEQ];
__device__ __align__(256) ushort_t g_xTl[NB * DIN * LSEQ];
__device__ __align__(256) float    g_Gp [NB * 4 * 512 * 512];
__device__ __align__(256) ushort_t g_Gh [NB * 512 * 512];
__device__ __align__(256) ushort_t g_Gl [NB * 512 * 512];
__device__ __align__(256) float    g_Pp [NB * 4 * 512 * 512];
__device__ __align__(256) ushort_t g_PTh[NB * 512 * 512];
__device__ __align__(256) ushort_t g_PTl[NB * 512 * 512];
__device__ __align__(256) ushort_t g_RTh[NB * NH * 64 * 64];
__device__ __align__(256) ushort_t g_RTl[NB * NH * 64 * 64];
__device__ __align__(256) ushort_t g_Uh [NB * 512 * 512];
__device__ __align__(256) ushort_t g_Ul [NB * 512 * 512];
__device__ __align__(256) float    g_Cp [NB * 4 * 512 * 512];
__device__ __align__(256) ushort_t g_CTh[NB * 512 * 512];
__device__ __align__(256) ushort_t g_CTl[NB * 512 * 512];
__device__ __align__(256) ushort_t g_Wkbh[512 * 512];     // [c=h*64+k][m]
__device__ __align__(256) ushort_t g_Wkbl[512 * 512];
__device__ __align__(256) ushort_t g_Wobh[512 * 512];     // [o][hv]
__device__ __align__(256) ushort_t g_Wobl[512 * 512];
__device__ __align__(256) ushort_t g_WvTh[512 * 512];     // [hv][n]
__device__ __align__(256) ushort_t g_WvTl[512 * 512];
__device__ __align__(256) ushort_t g_Wqbh[NH * 512 * 64]; // [h*512+j][k]
__device__ __align__(256) ushort_t g_Wqbl[NH * 512 * 64];

__device__ unsigned g_cnt = 0;
__device__ unsigned g_rel = 0;

// ---------------- helpers ----------------
#define SWZ(o) ((o) ^ (((o) >> 3) & 0x70))

__device__ __forceinline__ uint32_t smem_u32(const void* p) {
    uint32_t a;
    asm("{ .reg .u64 t; cvta.to.shared.u64 t, %1; cvt.u32.u64 %0, t; }" : "=r"(a) : "l"(p));
    return a;
}
__device__ __forceinline__ ushort_t f2bf(float v) {
    __nv_bfloat16 b = __float2bfloat16(v);
    return *reinterpret_cast<ushort_t*>(&b);
}
__device__ __forceinline__ float bfhi(ushort_t h) {
    return __uint_as_float(((uint32_t)h) << 16);
}
__device__ __forceinline__ void ldsm4(uint32_t* f, uint32_t addr) {
    asm volatile("ldmatrix.sync.aligned.m8n8.x4.shared.b16 {%0,%1,%2,%3}, [%4];"
                 : "=r"(f[0]), "=r"(f[1]), "=r"(f[2]), "=r"(f[3]) : "r"(addr));
}
__device__ __forceinline__ void mma16816(float* d, const uint32_t* a, const uint32_t* b) {
    asm volatile("mma.sync.aligned.m16n8k16.row.col.f32.bf16.bf16.f32 "
                 "{%0,%1,%2,%3}, {%4,%5,%6,%7}, {%8,%9}, {%0,%1,%2,%3};"
                 : "+f"(d[0]), "+f"(d[1]), "+f"(d[2]), "+f"(d[3])
                 : "r"(a[0]), "r"(a[1]), "r"(a[2]), "r"(a[3]), "r"(b[0]), "r"(b[1]));
}
__device__ __forceinline__ void cpa16(uint32_t s, const void* g) {
    asm volatile("cp.async.cg.shared.global [%0], [%1], 16;" :: "r"(s), "l"(g) : "memory");
}
#define CP_COMMIT() asm volatile("cp.async.commit_group;" ::: "memory")
#define CP_WAIT(n)  asm volatile("cp.async.wait_group %0;" :: "n"(n) : "memory")

// Grid barrier: cumulative epoch, replay-safe (relbase snapshot at entry).
__device__ __forceinline__ void gbar(unsigned relbase, unsigned ph) {
    __syncthreads();
    if (threadIdx.x == 0) {
        __threadfence();
        unsigned a = atomicAdd(&g_cnt, 1u);
        if (a == NCTA - 1) {
            atomicExch(&g_cnt, 0u);
            __threadfence();
            atomicAdd(&g_rel, 1u);
        } else {
            while (atomicAdd(&g_rel, 0u) < relbase + ph) { __nanosleep(64); }
        }
        __threadfence();
    }
    __syncthreads();
}

// ===========================================================================
// 128x128 bf16x3 GEMM tile (HMMA), 4-stage cp.async pipeline, fp32 out.
// Pointers pre-offset to (m0,k0)/(n0,k0)/(m0,n0).
// ===========================================================================
__device__ __noinline__ void gemm128(char* dsm, uint32_t sb,
        const ushort_t* pAh, const ushort_t* pAl,
        const ushort_t* pBh, const ushort_t* pBl,
        float* pC, int K, int lda, int ldb, int ldc) {
    constexpr int SS = 32768, NSTG = 4;
    int tid = threadIdx.x, lane = tid & 31, wid = tid >> 5;
    int wm = wid & 1, wn = wid >> 1;

    float acc[4][4][4];
#pragma unroll
    for (int i = 0; i < 4; i++)
#pragma unroll
        for (int j = 0; j < 4; j++)
#pragma unroll
            for (int q = 0; q < 4; q++) acc[i][j][q] = 0.f;

    const int nkt = K >> 5;

    auto load_stage = [&](int stg, int kt, bool pred) {
        if (pred) {
            uint32_t s0 = sb + stg * SS;
            int ke = kt * 32;
#pragma unroll
            for (int c = tid; c < 512; c += 256) {
                int r = c >> 2, sg = c & 3;
                uint32_t o = SWZ((uint32_t)((r >> 1) * 128 + (r & 1) * 64 + sg * 16));
                cpa16(s0 + o,        pAh + (size_t)r * lda + ke + sg * 8);
                cpa16(s0 + 8192 + o, pAl + (size_t)r * lda + ke + sg * 8);
            }
#pragma unroll
            for (int c = tid; c < 512; c += 256) {
                int r = c >> 2, sg = c & 3;
                uint32_t o = SWZ((uint32_t)((r >> 1) * 128 + (r & 1) * 64 + sg * 16));
                cpa16(s0 + 16384 + o, pBh + (size_t)r * ldb + ke + sg * 8);
                cpa16(s0 + 24576 + o, pBl + (size_t)r * ldb + ke + sg * 8);
            }
        }
        CP_COMMIT();
    };

#pragma unroll
    for (int s = 0; s < NSTG - 1; s++) load_stage(s, s, s < nkt);

#pragma unroll 1
    for (int kt = 0; kt < nkt; kt++) {
        CP_WAIT(2);
        __syncthreads();
        load_stage((kt + NSTG - 1) & (NSTG - 1), kt + NSTG - 1, kt + NSTG - 1 < nkt);

        uint32_t stb = sb + (kt & (NSTG - 1)) * SS;
#pragma unroll
        for (int ks = 0; ks < 2; ks++) {
            uint32_t ah[4][4], al[4][4], bh[2][4], bl[2][4];
            int ar  = wm * 64 + (lane & 15);
            int akk = ks * 16 + (lane >> 4) * 8;
#pragma unroll
            for (int mt = 0; mt < 4; mt++) {
                int r = ar + mt * 16;
                uint32_t o = SWZ((uint32_t)((r >> 1) * 128 + (r & 1) * 64 + akk * 2));
                ldsm4(ah[mt], stb + o);
                ldsm4(al[mt], stb + 8192 + o);
            }
            int bn  = wn * 32 + (lane & 7) + ((lane >> 4) & 1) * 8;
            int bkk = ks * 16 + ((lane >> 3) & 1) * 8;
#pragma unroll
            for (int p = 0; p < 2; p++) {
                int r = bn + p * 16;
                uint32_t o = SWZ((uint32_t)((r >> 1) * 128 + (r & 1) * 64 + bkk * 2));
                ldsm4(bh[p], stb + 16384 + o);
                ldsm4(bl[p], stb + 24576 + o);
            }
#pragma unroll
            for (int mt = 0; mt < 4; mt++)
#pragma unroll
                for (int nt = 0; nt < 4; nt++) {
                    const uint32_t* fh = &bh[nt >> 1][(nt & 1) * 2];
                    const uint32_t* fl = &bl[nt >> 1][(nt & 1) * 2];
                    mma16816(acc[mt][nt], ah[mt], fh);
                    mma16816(acc[mt][nt], al[mt], fh);
                    mma16816(acc[mt][nt], ah[mt], fl);
                }
        }
    }

    int r0 = wm * 64 + (lane >> 2);
    int c0 = wn * 32 + (lane & 3) * 2;
#pragma unroll
    for (int mt = 0; mt < 4; mt++)
#pragma unroll
        for (int nt = 0; nt < 4; nt++) {
            int r = r0 + mt * 16, c = c0 + nt * 8;
            *(float2*)&pC[(size_t)r * ldc + c] =
                make_float2(acc[mt][nt][0], acc[mt][nt][1]);
            *(float2*)&pC[(size_t)(r + 8) * ldc + c] =
                make_float2(acc[mt][nt][2], acc[mt][nt][3]);
        }
    __syncthreads();
}

// split-4 fp32 reduce -> bf16 hi/lo
__device__ __forceinline__ void reduce4(const float* src, ushort_t* oh, ushort_t* ol,
                                        int cta, int tid) {
    for (int i = cta * 256 + tid; i < NB * 65536; i += NCTA * 256) {
        int b = i >> 16, e = i & 65535;
        const float4* p = (const float4*)src;
        float4 v = p[(size_t)(b * 4) * 65536 + e];
#pragma unroll
        for (int q = 1; q < 4; q++) {
            float4 t = p[(size_t)(b * 4 + q) * 65536 + e];
            v.x += t.x; v.y += t.y; v.z += t.z; v.w += t.w;
        }
        ushort_t h0 = f2bf(v.x), h1 = f2bf(v.y), h2 = f2bf(v.z), h3 = f2bf(v.w);
        size_t o = (size_t)b * 65536 + e;
        ((ushort4*)oh)[o] = make_ushort4(h0, h1, h2, h3);
        ((ushort4*)ol)[o] = make_ushort4(f2bf(v.x - bfhi(h0)), f2bf(v.y - bfhi(h1)),
                                         f2bf(v.z - bfhi(h2)), f2bf(v.w - bfhi(h3)));
    }
}

// ===========================================================================
// THE persistent kernel
// ===========================================================================
__global__ void __launch_bounds__(256, 1)
attn_all(const float* __restrict__ x, const float* __restrict__ Wq,
         const float* __restrict__ Wk, const float* __restrict__ Wv,
         const float* __restrict__ Wo, float* __restrict__ out) {
    extern __shared__ char dsm[];
    uint32_t sb = smem_u32(dsm);
    int tid = threadIdx.x, cta = blockIdx.x;
    unsigned relbase = 0;
    if (tid == 0) relbase = atomicAdd(&g_rel, 0u);

    // ============ P0: pack all inputs ============
    {   // xT 64x64 tiles: 1024 tasks
        float* S = (float*)dsm;          // [64][65]
        for (int t = cta; t < 1024; t += NCTA) {
            int b = t >> 9, rem = t & 511, lt = rem >> 3, dt = rem & 7;
            const float* xb = x + (size_t)b * bX + (size_t)(lt * 64) * DIN + dt * 64;
            {
                int r = tid >> 2, c0 = (tid & 3) * 16;
                const float4* src = (const float4*)(xb + (size_t)r * DIN + c0);
                float* Sr = S + r * 65 + c0;
#pragma unroll
                for (int q = 0; q < 4; q++) {
                    float4 v = src[q];
                    Sr[q*4+0] = v.x; Sr[q*4+1] = v.y; Sr[q*4+2] = v.z; Sr[q*4+3] = v.w;
                }
            }
            __syncthreads();
            {
                int d = tid >> 2, ls = (tid & 3) * 16;
                ushort_t hb[16], lb[16];
#pragma unroll
                for (int q = 0; q < 16; q++) {
                    float v = S[(ls + q) * 65 + d];
                    ushort_t h = f2bf(v);
                    hb[q] = h; lb[q] = f2bf(v - bfhi(h));
                }
                size_t o = ((size_t)b * 512 + dt * 64 + d) * 4096 + lt * 64 + ls;
                *(uint4*)&g_xTh[o]     = ((uint4*)hb)[0];
                *(uint4*)&g_xTh[o + 8] = ((uint4*)hb)[1];
                *(uint4*)&g_xTl[o]     = ((uint4*)lb)[0];
                *(uint4*)&g_xTl[o + 8] = ((uint4*)lb)[1];
            }
            __syncthreads();
        }
    }
    for (int i = cta * 256 + tid; i < (int)(NB * bX / 4); i += NCTA * 256) {
        float4 v = ((const float4*)x)[i];
        ushort_t h0 = f2bf(v.x), h1 = f2bf(v.y), h2 = f2bf(v.z), h3 = f2bf(v.w);
        ((ushort4*)g_xh)[i] = make_ushort4(h0, h1, h2, h3);
        ((ushort4*)g_xl)[i] = make_ushort4(f2bf(v.x - bfhi(h0)), f2bf(v.y - bfhi(h1)),
                                           f2bf(v.z - bfhi(h2)), f2bf(v.w - bfhi(h3)));
    }
    for (int i = cta * 256 + tid; i < 65536; i += NCTA * 256) {   // Wqb straight
        float4 v = ((const float4*)Wq)[i];
        ushort_t h0 = f2bf(v.x), h1 = f2bf(v.y), h2 = f2bf(v.z), h3 = f2bf(v.w);
        ((ushort4*)g_Wqbh)[i] = make_ushort4(h0, h1, h2, h3);
        ((ushort4*)g_Wqbl)[i] = make_ushort4(f2bf(v.x - bfhi(h0)), f2bf(v.y - bfhi(h1)),
                                             f2bf(v.z - bfhi(h2)), f2bf(v.w - bfhi(h3)));
    }
    for (int i = cta * 256 + tid; i < 65536; i += NCTA * 256) {   // Wkb[c][m]
        int flat = i * 4, c = flat >> 9, m = flat & 511;
        int h = c >> 6, kd = c & 63;
        const float* ws = Wk + h * 32768 + kd;
        float e0 = ws[(m+0)*64], e1 = ws[(m+1)*64], e2 = ws[(m+2)*64], e3 = ws[(m+3)*64];
        ushort_t h0 = f2bf(e0), h1 = f2bf(e1), h2 = f2bf(e2), h3 = f2bf(e3);
        ((ushort4*)g_Wkbh)[i] = make_ushort4(h0, h1, h2, h3);
        ((ushort4*)g_Wkbl)[i] = make_ushort4(f2bf(e0 - bfhi(h0)), f2bf(e1 - bfhi(h1)),
                                             f2bf(e2 - bfhi(h2)), f2bf(e3 - bfhi(h3)));
    }
    for (int i = cta * 256 + tid; i < 65536; i += NCTA * 256) {   // Wob[o][hv]
        int flat = i * 4, o = flat >> 9, hv = flat & 511;
        float e0 = Wo[(hv+0)*512 + o], e1 = Wo[(hv+1)*512 + o];
        float e2 = Wo[(hv+2)*512 + o], e3 = Wo[(hv+3)*512 + o];
        ushort_t h0 = f2bf(e0), h1 = f2bf(e1), h2 = f2bf(e2), h3 = f2bf(e3);
        ((ushort4*)g_Wobh)[i] = make_ushort4(h0, h1, h2, h3);
        ((ushort4*)g_Wobl)[i] = make_ushort4(f2bf(e0 - bfhi(h0)), f2bf(e1 - bfhi(h1)),
                                             f2bf(e2 - bfhi(h2)), f2bf(e3 - bfhi(h3)));
    }
    for (int i = cta * 256 + tid; i < 65536; i += NCTA * 256) {   // WvT[hv][n]
        int flat = i * 4, row = flat >> 9, n = flat & 511;
        int h = row >> 6, vv = row & 63;
        const float* ws = Wv + h * 32768 + vv;
        float e0 = ws[(n+0)*64], e1 = ws[(n+1)*64], e2 = ws[(n+2)*64], e3 = ws[(n+3)*64];
        ushort_t h0 = f2bf(e0), h1 = f2bf(e1), h2 = f2bf(e2), h3 = f2bf(e3);
        ((ushort4*)g_WvTh)[i] = make_ushort4(h0, h1, h2, h3);
        ((ushort4*)g_WvTl)[i] = make_ushort4(f2bf(e0 - bfhi(h0)), f2bf(e1 - bfhi(h1)),
                                             f2bf(e2 - bfhi(h2)), f2bf(e3 - bfhi(h3)));
    }
    gbar(relbase, 1);

    // ============ P1: G = xT @ xT^T (split-K 4) ============
    {
        int sl = cta & 3, ti = (cta >> 2) & 15, b = cta >> 6;
        int m0 = (ti >> 2) * 128, n0 = (ti & 3) * 128;
        const ushort_t* bh_ = g_xTh + (size_t)b * DIN * LSEQ;
        const ushort_t* bl_ = g_xTl + (size_t)b * DIN * LSEQ;
        gemm128(dsm, sb,
                bh_ + (size_t)m0 * 4096 + sl * 1024, bl_ + (size_t)m0 * 4096 + sl * 1024,
                bh_ + (size_t)n0 * 4096 + sl * 1024, bl_ + (size_t)n0 * 4096 + sl * 1024,
                g_Gp + (size_t)(b * 4 + sl) * bS + (size_t)m0 * 512 + n0,
                1024, 4096, 4096, 512);
    }
    gbar(relbase, 2);
    reduce4(g_Gp, g_Gh, g_Gl, cta, tid);
    gbar(relbase, 3);

    // ============ P3: PT = Wkb @ G (split-K 4) ============
    {
        int sl = cta & 3, ti = (cta >> 2) & 15, b = cta >> 6;
        int m0 = (ti >> 2) * 128, n0 = (ti & 3) * 128;
        gemm128(dsm, sb,
                g_Wkbh + (size_t)m0 * 512 + sl * 128, g_Wkbl + (size_t)m0 * 512 + sl * 128,
                g_Gh + (size_t)b * bS + (size_t)n0 * 512 + sl * 128,
                g_Gl + (size_t)b * bS + (size_t)n0 * 512 + sl * 128,
                g_Pp + (size_t)(b * 4 + sl) * bS + (size_t)m0 * 512 + n0,
                128, 512, 512, 512);
    }
    gbar(relbase, 4);
    reduce4(g_Pp, g_PTh, g_PTl, cta, tid);
    gbar(relbase, 5);

    // ============ P5: RT[v][k] = sum_n WvT[hv][n] * PT[hk][n] ============
    {
        float* As = (float*)dsm;        // [8][512]
        int b = cta >> 6, h = (cta >> 3) & 7, vs = cta & 7;
        int row0 = h * 64 + vs * 8;
        for (int i = tid; i < 8 * 128; i += 256) {
            int r = i >> 7, c4 = (i & 127) * 4;
            ushort4 hv = *(const ushort4*)&g_WvTh[(size_t)(row0 + r) * 512 + c4];
            ushort4 lv = *(const ushort4*)&g_WvTl[(size_t)(row0 + r) * 512 + c4];
            *(float4*)&As[r * 512 + c4] =
                make_float4(bfhi(hv.x) + bfhi(lv.x), bfhi(hv.y) + bfhi(lv.y),
                            bfhi(hv.z) + bfhi(lv.z), bfhi(hv.w) + bfhi(lv.w));
        }
        __syncthreads();
        int k = tid & 63, vp = tid >> 6;
        const ushort4* Bh4 = (const ushort4*)(g_PTh + (size_t)b * bS + (size_t)(h * 64 + k) * 512);
        const ushort4* Bl4 = (const ushort4*)(g_PTl + (size_t)b * bS + (size_t)(h * 64 + k) * 512);
        const float4* A0 = (const float4*)(As + (vp * 2 + 0) * 512);
        const float4* A1 = (const float4*)(As + (vp * 2 + 1) * 512);
        float a0 = 0.f, a1 = 0.f;
#pragma unroll 4
        for (int n4 = 0; n4 < 128; n4++) {
            ushort4 bh4 = Bh4[n4], bl4 = Bl4[n4];
            float4 bv = make_float4(bfhi(bh4.x) + bfhi(bl4.x), bfhi(bh4.y) + bfhi(bl4.y),
                                    bfhi(bh4.z) + bfhi(bl4.z), bfhi(bh4.w) + bfhi(bl4.w));
            float4 x0 = A0[n4], x1 = A1[n4];
            a0 += x0.x*bv.x + x0.y*bv.y + x0.z*bv.z + x0.w*bv.w;
            a1 += x1.x*bv.x + x1.y*bv.y + x1.z*bv.z + x1.w*bv.w;
        }
        size_t base = (size_t)(b * 8 + h) * 4096 + (size_t)vs * 8 * 64;
        ushort_t h0 = f2bf(a0), h1 = f2bf(a1);
        g_RTh[base + (vp * 2 + 0) * 64 + k] = h0;
        g_RTl[base + (vp * 2 + 0) * 64 + k] = f2bf(a0 - bfhi(h0));
        g_RTh[base + (vp * 2 + 1) * 64 + k] = h1;
        g_RTl[base + (vp * 2 + 1) * 64 + k] = f2bf(a1 - bfhi(h1));
        __syncthreads();
    }
    gbar(relbase, 6);

    // ============ P6: U[j][h*64+v] = sum_k Wqb[h*512+j][k] * RT[v][k] ============
    {
        float* As = (float*)dsm;                 // [64][69]
        float* Bs = As + 64 * 69;                // [64][69]
        int b = cta >> 6, h = (cta >> 3) & 7, j0 = cta & 7;
        const ushort_t* Ah = g_Wqbh + ((size_t)h * 512 + j0 * 64) * 64;
        const ushort_t* Al = g_Wqbl + ((size_t)h * 512 + j0 * 64) * 64;
        const ushort_t* Bh = g_RTh + (size_t)(b * 8 + h) * 4096;
        const ushort_t* Bl = g_RTl + (size_t)(b * 8 + h) * 4096;
        for (int i = tid; i < 64 * 16; i += 256) {
            int r = i >> 4, c4 = (i & 15) * 4;
            ushort4 a4 = *(const ushort4*)&Ah[r * 64 + c4];
            ushort4 l4 = *(const ushort4*)&Al[r * 64 + c4];
            As[r * 69 + c4+0] = bfhi(a4.x) + bfhi(l4.x);
            As[r * 69 + c4+1] = bfhi(a4.y) + bfhi(l4.y);
            As[r * 69 + c4+2] = bfhi(a4.z) + bfhi(l4.z);
            As[r * 69 + c4+3] = bfhi(a4.w) + bfhi(l4.w);
            ushort4 b4 = *(const ushort4*)&Bh[r * 64 + c4];
            ushort4 m4 = *(const ushort4*)&Bl[r * 64 + c4];
            Bs[r * 69 + c4+0] = bfhi(b4.x) + bfhi(m4.x);
            Bs[r * 69 + c4+1] = bfhi(b4.y) + bfhi(m4.y);
            Bs[r * 69 + c4+2] = bfhi(b4.z) + bfhi(m4.z);
            Bs[r * 69 + c4+3] = bfhi(b4.w) + bfhi(m4.w);
        }
        __syncthreads();
        int tx = tid & 15, ty = tid >> 4;
        float acc[4][4] = {};
#pragma unroll 8
        for (int k = 0; k < 64; k++) {
            float a[4], bb[4];
#pragma unroll
            for (int i = 0; i < 4; i++) a[i]  = As[(ty * 4 + i) * 69 + k];
#pragma unroll
            for (int j = 0; j < 4; j++) bb[j] = Bs[(tx * 4 + j) * 69 + k];
#pragma unroll
            for (int i = 0; i < 4; i++)
#pragma unroll
                for (int j = 0; j < 4; j++) acc[i][j] += a[i] * bb[j];
        }
        size_t ub = (size_t)b * bS;
#pragma unroll
        for (int i = 0; i < 4; i++) {
            int jg = j0 * 64 + ty * 4 + i;
            ushort_t hb[4], lb[4];
#pragma unroll
            for (int j = 0; j < 4; j++) {
                ushort_t hh = f2bf(acc[i][j]);
                hb[j] = hh; lb[j] = f2bf(acc[i][j] - bfhi(hh));
            }
            size_t o = ub + (size_t)jg * 512 + h * 64 + tx * 4;
            *(ushort4*)&g_Uh[o] = make_ushort4(hb[0], hb[1], hb[2], hb[3]);
            *(ushort4*)&g_Ul[o] = make_ushort4(lb[0], lb[1], lb[2], lb[3]);
        }
        __syncthreads();
    }
    gbar(relbase, 7);

    // ============ P7: CT = Wob @ U (split-K 4) ============
    {
        int sl = cta & 3, ti = (cta >> 2) & 15, b = cta >> 6;
        int m0 = (ti >> 2) * 128, n0 = (ti & 3) * 128;
        gemm128(dsm, sb,
                g_Wobh + (size_t)m0 * 512 + sl * 128, g_Wobl + (size_t)m0 * 512 + sl * 128,
                g_Uh + (size_t)b * bS + (size_t)n0 * 512 + sl * 128,
                g_Ul + (size_t)b * bS + (size_t)n0 * 512 + sl * 128,
                g_Cp + (size_t)(b * 4 + sl) * bS + (size_t)m0 * 512 + n0,
                128, 512, 512, 512);
    }
    gbar(relbase, 8);
    reduce4(g_Cp, g_CTh, g_CTl, cta, tid);
    gbar(relbase, 9);

    // ============ P9: out = x @ CT^T  (2 tiles per CTA) ============
#pragma unroll 1
    for (int q = 0; q < 2; q++) {
        int t = cta + q * NCTA;              // 256 tasks: b = t>>7
        int b = t >> 7, lt = (t >> 2) & 31, ot = t & 3;
        int l0 = lt * 128, o0 = ot * 128;
        gemm128(dsm, sb,
                g_xh + (size_t)b * bX + (size_t)l0 * 512,
                g_xl + (size_t)b * bX + (size_t)l0 * 512,
                g_CTh + (size_t)b * bS + (size_t)o0 * 512,
                g_CTl + (size_t)b * bS + (size_t)o0 * 512,
                out + (size_t)b * bX + (size_t)l0 * 512 + o0,
                512, 512, 512, 512);
    }
}

// ===========================================================================
extern "C" void kernel_launch(void* const* d_in, const int* in_sizes, int n_in,
                              void* d_out, int out_size) {
    const float* x  = (const float*)d_in[0];
    const float* Wq = (const float*)d_in[1];
    const float* Wk = (const float*)d_in[2];
    const float* Wv = (const float*)d_in[3];
    const float* Wo = (const float*)d_in[4];
    float* out = (float*)d_out;

    cudaFuncSetAttribute(attn_all, cudaFuncAttributeMaxDynamicSharedMemorySize, 131072);
    attn_all<<<NCTA, 256, 131072>>>(x, Wq, Wk, Wv, Wo, out);
}

// round 10
// speedup vs baseline: 1.2960x; 1.2960x over previous
#include <cuda_runtime.h>
#include <cuda_bf16.h>
#include <cstdint>

#define LSEQ 4096
#define DIN  512
#define NH   8
#define NB   2

typedef unsigned short ushort_t;
static const size_t bS = 512 * 512;
static const size_t bX = (size_t)LSEQ * DIN;

// ---------------- device scratch ----------------
__device__ __align__(256) ushort_t g_xh [NB * LSEQ * DIN];
__device__ __align__(256) ushort_t g_xl [NB * LSEQ * DIN];
__device__ __align__(256) ushort_t g_xTh[NB * DIN * LSEQ];
__device__ __align__(256) ushort_t g_xTl[NB * DIN * LSEQ];
__device__ __align__(256) float    g_Gp [NB * 4 * 512 * 512];
__device__ __align__(256) ushort_t g_Gh [NB * 512 * 512];
__device__ __align__(256) ushort_t g_Gl [NB * 512 * 512];
__device__ __align__(256) ushort_t g_PTh[NB * 512 * 512];
__device__ __align__(256) ushort_t g_PTl[NB * 512 * 512];
__device__ __align__(256) ushort_t g_RTh[NB * NH * 64 * 64];
__device__ __align__(256) ushort_t g_RTl[NB * NH * 64 * 64];
__device__ __align__(256) ushort_t g_Uh [NB * 512 * 512];
__device__ __align__(256) ushort_t g_Ul [NB * 512 * 512];
__device__ __align__(256) ushort_t g_CTh[NB * 512 * 512];
__device__ __align__(256) ushort_t g_CTl[NB * 512 * 512];
__device__ __align__(256) ushort_t g_Wkbh[512 * 512];     // [c=h*64+k][m]
__device__ __align__(256) ushort_t g_Wkbl[512 * 512];
__device__ __align__(256) ushort_t g_Wobh[512 * 512];     // [o][hv]
__device__ __align__(256) ushort_t g_Wobl[512 * 512];
__device__ __align__(256) ushort_t g_WvTh[512 * 512];     // [hv][n]
__device__ __align__(256) ushort_t g_WvTl[512 * 512];
__device__ __align__(256) ushort_t g_Wqbh[NH * 512 * 64]; // [h*512+j][k]
__device__ __align__(256) ushort_t g_Wqbl[NH * 512 * 64];

// ---------------- helpers ----------------
#define SWZ(o) ((o) ^ (((o) >> 3) & 0x70))

__device__ __forceinline__ uint32_t smem_u32(const void* p) {
    uint32_t a;
    asm("{ .reg .u64 t; cvta.to.shared.u64 t, %1; cvt.u32.u64 %0, t; }" : "=r"(a) : "l"(p));
    return a;
}
__device__ __forceinline__ ushort_t f2bf(float v) {
    __nv_bfloat16 b = __float2bfloat16(v);
    return *reinterpret_cast<ushort_t*>(&b);
}
__device__ __forceinline__ float bfhi(ushort_t h) {
    return __uint_as_float(((uint32_t)h) << 16);
}
__device__ __forceinline__ void ldsm4(uint32_t* f, uint32_t addr) {
    asm volatile("ldmatrix.sync.aligned.m8n8.x4.shared.b16 {%0,%1,%2,%3}, [%4];"
                 : "=r"(f[0]), "=r"(f[1]), "=r"(f[2]), "=r"(f[3]) : "r"(addr));
}
__device__ __forceinline__ void mma16816(float* d, const uint32_t* a, const uint32_t* b) {
    asm volatile("mma.sync.aligned.m16n8k16.row.col.f32.bf16.bf16.f32 "
                 "{%0,%1,%2,%3}, {%4,%5,%6,%7}, {%8,%9}, {%0,%1,%2,%3};"
                 : "+f"(d[0]), "+f"(d[1]), "+f"(d[2]), "+f"(d[3])
                 : "r"(a[0]), "r"(a[1]), "r"(a[2]), "r"(a[3]), "r"(b[0]), "r"(b[1]));
}
__device__ __forceinline__ void cpa16(uint32_t s, const void* g) {
    asm volatile("cp.async.cg.shared.global [%0], [%1], 16;" :: "r"(s), "l"(g) : "memory");
}
#define CP_COMMIT() asm volatile("cp.async.commit_group;" ::: "memory")
#define CP_WAIT(n)  asm volatile("cp.async.wait_group %0;" :: "n"(n) : "memory")

// ===========================================================================
// Generic bf16x3 GEMM via mma.sync (HMMA): C(m,n) = sum_k A(m,k)*B(n,k).
// A, B pre-split bf16 hi/lo, K contiguous. 256 threads, warp grid 2(m)x4(n).
// 4-stage cp.async pipeline, ONE __syncthreads per ktile.
// EPI 0: fp32 row-major out. EPI 1: bf16 hi/lo row-major out.
// ===========================================================================
template <int BM, int BN, int EPI>
__global__ void __launch_bounds__(256, 1)
gemm_bf3(const ushort_t* __restrict__ Ah, const ushort_t* __restrict__ Al,
         const ushort_t* __restrict__ Bh, const ushort_t* __restrict__ Bl,
         float* __restrict__ Cf, ushort_t* __restrict__ Ch, ushort_t* __restrict__ Cl,
         int K, int lda, int ldb, int ldc,
         long bA, long slA, long bB, long slB, long bC, long slC, int nsl) {
    constexpr int WM = BM / 2, WN = BN / 4;
    constexpr int MT = WM / 16, NT = WN / 8, PB = WN / 16;
    constexpr int SS = (BM + BN) * 128;          // stage bytes: Ah|Al|Bh|Bl
    constexpr int NSTG = 4;

    extern __shared__ char dsm[];
    uint32_t sb = smem_u32(dsm);
    int tid = threadIdx.x, lane = tid & 31, wid = tid >> 5;
    int wm = wid & 1, wn = wid >> 1;

    int z = blockIdx.z, b = z / nsl, sl = z - b * nsl;
    int m0 = blockIdx.y * BM, n0 = blockIdx.x * BN;
    const ushort_t* pAh = Ah + b * bA + sl * slA + (size_t)m0 * lda;
    const ushort_t* pAl = Al + b * bA + sl * slA + (size_t)m0 * lda;
    const ushort_t* pBh = Bh + b * bB + sl * slB + (size_t)n0 * ldb;
    const ushort_t* pBl = Bl + b * bB + sl * slB + (size_t)n0 * ldb;

    float acc[MT][NT][4];
#pragma unroll
    for (int i = 0; i < MT; i++)
#pragma unroll
        for (int j = 0; j < NT; j++)
#pragma unroll
            for (int q = 0; q < 4; q++) acc[i][j][q] = 0.f;

    const int nkt = K >> 5;

    auto load_stage = [&](int stg, int kt, bool pred) {
        if (pred) {
            uint32_t s0 = sb + stg * SS;
            int ke = kt * 32;
#pragma unroll
            for (int c = tid; c < BM * 4; c += 256) {
                int r = c >> 2, sg = c & 3;
                uint32_t o = SWZ((uint32_t)((r >> 1) * 128 + (r & 1) * 64 + sg * 16));
                cpa16(s0 + o,           pAh + (size_t)r * lda + ke + sg * 8);
                cpa16(s0 + BM * 64 + o, pAl + (size_t)r * lda + ke + sg * 8);
            }
#pragma unroll
            for (int c = tid; c < BN * 4; c += 256) {
                int r = c >> 2, sg = c & 3;
                uint32_t o = SWZ((uint32_t)((r >> 1) * 128 + (r & 1) * 64 + sg * 16));
                cpa16(s0 + BM * 128 + o,           pBh + (size_t)r * ldb + ke + sg * 8);
                cpa16(s0 + BM * 128 + BN * 64 + o, pBl + (size_t)r * ldb + ke + sg * 8);
            }
        }
        CP_COMMIT();
    };

#pragma unroll
    for (int s = 0; s < NSTG - 1; s++) load_stage(s, s, s < nkt);

#pragma unroll 1
    for (int kt = 0; kt < nkt; kt++) {
        CP_WAIT(2);
        __syncthreads();
        load_stage((kt + NSTG - 1) & (NSTG - 1), kt + NSTG - 1, kt + NSTG - 1 < nkt);

        uint32_t stb = sb + (kt & (NSTG - 1)) * SS;
#pragma unroll
        for (int ks = 0; ks < 2; ks++) {
            uint32_t ah[MT][4], al[MT][4], bh[PB][4], bl[PB][4];
            int ar  = wm * WM + (lane & 15);
            int akk = ks * 16 + (lane >> 4) * 8;
#pragma unroll
            for (int mt = 0; mt < MT; mt++) {
                int r = ar + mt * 16;
                uint32_t o = SWZ((uint32_t)((r >> 1) * 128 + (r & 1) * 64 + akk * 2));
                ldsm4(ah[mt], stb + o);
                ldsm4(al[mt], stb + BM * 64 + o);
            }
            int bn  = wn * WN + (lane & 7) + ((lane >> 4) & 1) * 8;
            int bkk = ks * 16 + ((lane >> 3) & 1) * 8;
#pragma unroll
            for (int p = 0; p < PB; p++) {
                int r = bn + p * 16;
                uint32_t o = SWZ((uint32_t)((r >> 1) * 128 + (r & 1) * 64 + bkk * 2));
                ldsm4(bh[p], stb + BM * 128 + o);
                ldsm4(bl[p], stb + BM * 128 + BN * 64 + o);
            }
#pragma unroll
            for (int mt = 0; mt < MT; mt++)
#pragma unroll
                for (int nt = 0; nt < NT; nt++) {
                    const uint32_t* fh = &bh[nt >> 1][(nt & 1) * 2];
                    const uint32_t* fl = &bl[nt >> 1][(nt & 1) * 2];
                    mma16816(acc[mt][nt], ah[mt], fh);
                    mma16816(acc[mt][nt], al[mt], fh);
                    mma16816(acc[mt][nt], ah[mt], fl);
                }
        }
    }

    long offC = b * bC + sl * slC;
    int r0 = m0 + wm * WM + (lane >> 2);
    int c0 = n0 + wn * WN + (lane & 3) * 2;
    if (EPI == 0) {
        float* Co = Cf + offC;
#pragma unroll
        for (int mt = 0; mt < MT; mt++)
#pragma unroll
            for (int nt = 0; nt < NT; nt++) {
                int r = r0 + mt * 16, c = c0 + nt * 8;
                *(float2*)&Co[(size_t)r * ldc + c] =
                    make_float2(acc[mt][nt][0], acc[mt][nt][1]);
                *(float2*)&Co[(size_t)(r + 8) * ldc + c] =
                    make_float2(acc[mt][nt][2], acc[mt][nt][3]);
            }
    } else {
        ushort_t* Hh = Ch + offC;
        ushort_t* Hl = Cl + offC;
#pragma unroll
        for (int mt = 0; mt < MT; mt++)
#pragma unroll
            for (int nt = 0; nt < NT; nt++)
#pragma unroll
                for (int hf = 0; hf < 2; hf++) {
                    int r = r0 + mt * 16 + hf * 8, c = c0 + nt * 8;
                    float v0 = acc[mt][nt][hf * 2], v1 = acc[mt][nt][hf * 2 + 1];
                    ushort_t h0 = f2bf(v0), h1 = f2bf(v1);
                    *(ushort2*)&Hh[(size_t)r * ldc + c] = make_ushort2(h0, h1);
                    *(ushort2*)&Hl[(size_t)r * ldc + c] =
                        make_ushort2(f2bf(v0 - bfhi(h0)), f2bf(v1 - bfhi(h1)));
                }
    }
}

// ===========================================================================
// Fused input pack
// ===========================================================================
__global__ void pack_all(const float* __restrict__ x, const float* __restrict__ Wq,
                         const float* __restrict__ Wk, const float* __restrict__ Wv,
                         const float* __restrict__ Wo) {
    __shared__ float s[32][33];
    int blk = blockIdx.x, tid = threadIdx.x;
    if (blk < 4096) {                      // x row-major split
        size_t i = (size_t)blk * 256 + tid;
        float4 v = ((const float4*)x)[i];
        ushort_t h0 = f2bf(v.x), h1 = f2bf(v.y), h2 = f2bf(v.z), h3 = f2bf(v.w);
        ((ushort4*)g_xh)[i] = make_ushort4(h0, h1, h2, h3);
        ((ushort4*)g_xl)[i] = make_ushort4(f2bf(v.x - bfhi(h0)), f2bf(v.y - bfhi(h1)),
                                           f2bf(v.z - bfhi(h2)), f2bf(v.w - bfhi(h3)));
    } else if (blk < 8192) {               // x transpose -> xT[d][l]
        int id = blk - 4096;
        int bx = id & 127, by = (id >> 7) & 15, b = id >> 11;
        int r0 = bx * 32, c0 = by * 32;
        int tx = tid & 31, ty = tid >> 5;
        const float* xb = x + (size_t)b * bX;
#pragma unroll
        for (int q = 0; q < 4; q++)
            s[ty + 8 * q][tx] = xb[(size_t)(r0 + ty + 8 * q) * DIN + c0 + tx];
        __syncthreads();
#pragma unroll
        for (int q = 0; q < 4; q++) {
            int cd = ty + 8 * q;
            float v = s[tx][cd];
            ushort_t h = f2bf(v);
            size_t o = ((size_t)b * DIN + c0 + cd) * LSEQ + r0 + tx;
            g_xTh[o] = h;
            g_xTl[o] = f2bf(v - bfhi(h));
        }
    } else if (blk < 9216) {               // Wkb[c][m] = Wk[h][m][k]
        int i = (blk - 8192) * 256 + tid;
        int c = i >> 9, m = i & 511, h = c >> 6, kd = c & 63;
        float v = Wk[h * 32768 + m * 64 + kd];
        ushort_t hh = f2bf(v);
        g_Wkbh[i] = hh; g_Wkbl[i] = f2bf(v - bfhi(hh));
    } else if (blk < 10240) {              // Wob[o][hv] = Wo[hv][o]
        int i = (blk - 9216) * 256 + tid;
        int o = i >> 9, hv = i & 511;
        float v = Wo[hv * 512 + o];
        ushort_t hh = f2bf(v);
        g_Wobh[i] = hh; g_Wobl[i] = f2bf(v - bfhi(hh));
    } else if (blk < 11264) {              // WvT[hv][n] = Wv[h][n][v]
        int i = (blk - 10240) * 256 + tid;
        int row = i >> 9, n = i & 511, h = row >> 6, vv = row & 63;
        float v = Wv[h * 32768 + n * 64 + vv];
        ushort_t hh = f2bf(v);
        g_WvTh[i] = hh; g_WvTl[i] = f2bf(v - bfhi(hh));
    } else {                               // Wqb straight split
        int i = (blk - 11264) * 256 + tid;
        float v = Wq[i];
        ushort_t hh = f2bf(v);
        g_Wqbh[i] = hh; g_Wqbl[i] = f2bf(v - bfhi(hh));
    }
}

// ===========================================================================
// Split-K reduce: sum 4 fp32 partials per batch, emit bf16 hi/lo.
// ===========================================================================
__global__ void reduce_4(const float* __restrict__ src,
                         ushort_t* __restrict__ oh, ushort_t* __restrict__ ol) {
    int i = blockIdx.x * 256 + threadIdx.x;          // over NB*65536 float4
    int b = i >> 16, e = i & 65535;
    const float4* p = (const float4*)src;
    float4 v = p[(size_t)(b * 4) * 65536 + e];
#pragma unroll
    for (int q = 1; q < 4; q++) {
        float4 t = p[(size_t)(b * 4 + q) * 65536 + e];
        v.x += t.x; v.y += t.y; v.z += t.z; v.w += t.w;
    }
    ushort_t h0 = f2bf(v.x), h1 = f2bf(v.y), h2 = f2bf(v.z), h3 = f2bf(v.w);
    size_t o = (size_t)b * 65536 + e;
    ((ushort4*)oh)[o] = make_ushort4(h0, h1, h2, h3);
    ((ushort4*)ol)[o] = make_ushort4(f2bf(v.x - bfhi(h0)), f2bf(v.y - bfhi(h1)),
                                     f2bf(v.z - bfhi(h2)), f2bf(v.w - bfhi(h3)));
}

// ===========================================================================
extern "C" void kernel_launch(void* const* d_in, const int* in_sizes, int n_in,
                              void* d_out, int out_size) {
    const float* x  = (const float*)d_in[0];
    const float* Wq = (const float*)d_in[1];
    const float* Wk = (const float*)d_in[2];
    const float* Wv = (const float*)d_in[3];
    const float* Wo = (const float*)d_in[4];
    float* out = (float*)d_out;

    cudaFuncSetAttribute(gemm_bf3<128,128,0>, cudaFuncAttributeMaxDynamicSharedMemorySize, 131072);
    cudaFuncSetAttribute(gemm_bf3<64,64,1>,   cudaFuncAttributeMaxDynamicSharedMemorySize, 65536);
    cudaFuncSetAttribute(gemm_bf3<128,64,1>,  cudaFuncAttributeMaxDynamicSharedMemorySize, 98304);

    ushort_t *xh,*xl,*xTh,*xTl,*Gh,*Gl,*PTh,*PTl,*RTh,*RTl,*Uh,*Ul,*CTh,*CTl;
    ushort_t *Wkbh,*Wkbl,*Wobh,*Wobl,*WvTh,*WvTl,*Wqbh,*Wqbl;
    float *Gp;
    cudaGetSymbolAddress((void**)&xh,  g_xh);  cudaGetSymbolAddress((void**)&xl,  g_xl);
    cudaGetSymbolAddress((void**)&xTh, g_xTh); cudaGetSymbolAddress((void**)&xTl, g_xTl);
    cudaGetSymbolAddress((void**)&Gh,  g_Gh);  cudaGetSymbolAddress((void**)&Gl,  g_Gl);
    cudaGetSymbolAddress((void**)&PTh, g_PTh); cudaGetSymbolAddress((void**)&PTl, g_PTl);
    cudaGetSymbolAddress((void**)&RTh, g_RTh); cudaGetSymbolAddress((void**)&RTl, g_RTl);
    cudaGetSymbolAddress((void**)&Uh,  g_Uh);  cudaGetSymbolAddress((void**)&Ul,  g_Ul);
    cudaGetSymbolAddress((void**)&CTh, g_CTh); cudaGetSymbolAddress((void**)&CTl, g_CTl);
    cudaGetSymbolAddress((void**)&Wkbh,g_Wkbh);cudaGetSymbolAddress((void**)&Wkbl,g_Wkbl);
    cudaGetSymbolAddress((void**)&Wobh,g_Wobh);cudaGetSymbolAddress((void**)&Wobl,g_Wobl);
    cudaGetSymbolAddress((void**)&WvTh,g_WvTh);cudaGetSymbolAddress((void**)&WvTl,g_WvTl);
    cudaGetSymbolAddress((void**)&Wqbh,g_Wqbh);cudaGetSymbolAddress((void**)&Wqbl,g_Wqbl);
    cudaGetSymbolAddress((void**)&Gp,  g_Gp);

    pack_all<<<12288, 256>>>(x, Wq, Wk, Wv, Wo);

    // G[n][m] = sum_l xT[n][l] xT[m][l]; split-K 4, fp32 partials
    gemm_bf3<128,128,0><<<dim3(4,4,8), 256, 131072>>>(
        xTh, xTl, xTh, xTl, Gp, nullptr, nullptr,
        1024, LSEQ, LSEQ, 512,
        (long)bX, 1024, (long)bX, 1024, (long)(4*bS), (long)bS, 4);
    reduce_4<<<512, 256>>>(Gp, Gh, Gl);

    // PT[c][n] = sum_m Wkb[c][m] G[n][m]; 64x64 tiles, no split-K, bf16 out
    gemm_bf3<64,64,1><<<dim3(8,8,NB), 256, 65536>>>(
        Wkbh, Wkbl, Gh, Gl, nullptr, PTh, PTl,
        512, 512, 512, 512,
        0, 0, (long)bS, 0, (long)bS, 0, 1);

    // RT[v][k](b,h) = sum_n WvT[hv][n] PT[hk][n]; batched (b,h)
    gemm_bf3<64,64,1><<<dim3(1,1,16), 256, 65536>>>(
        WvTh, WvTl, PTh, PTl, nullptr, RTh, RTl,
        512, 512, 512, 64,
        0, 32768, (long)bS, 32768, (long)(NH*4096), 4096, NH);

    // U[j][hv](b) = sum_k Wqb[hj][k] RT[v][k]; batched (b,h)
    gemm_bf3<128,64,1><<<dim3(1,4,16), 256, 98304>>>(
        Wqbh, Wqbl, RTh, RTl, nullptr, Uh, Ul,
        64, 64, 64, 512,
        0, 32768, (long)(NH*4096), 4096, (long)bS, 64, NH);

    // CT[o][j](b) = sum_hv Wob[o][hv] U[j][hv]; 64x64 tiles, no split-K
    gemm_bf3<64,64,1><<<dim3(8,8,NB), 256, 65536>>>(
        Wobh, Wobl, Uh, Ul, nullptr, CTh, CTl,
        512, 512, 512, 512,
        0, 0, (long)bS, 0, (long)bS, 0, 1);

    // out[l][o] = sum_j x[l][j] CT[o][j]
    gemm_bf3<128,128,0><<<dim3(4,32,2), 256, 131072>>>(
        xh, xl, CTh, CTl, out, nullptr, nullptr,
        512, 512, 512, 512,
        (long)bX, 0, (long)bS, 0, (long)bX, 0, 1);
}